// round 12
// baseline (speedup 1.0000x reference)
#include <cuda_runtime.h>
#include <cuda_bf16.h>
#include <cuda_fp16.h>
#include <cuda_fp8.h>
#include <math.h>
#include <stdint.h>

#define HID   512
#define G4    2048
#define BATCH 64
#define VOCAB 32000
#define SRC   50
#define TGT   49
#define NSTEP (SRC + TGT)

#define VT2    125               // 32000 / 256
#define MT2    25                // 3200 / 128
#define NTILES_L (MT2 * VT2)     // 3125 logits tiles
#define DROWS  (TGT * BATCH)     // 3136 decode rows
#define DROWS_PAD 3200
#define GXROWS (NSTEP * BATCH)   // 6336
#define XROWS_PAD 6400
#define PCTAS 64                 // recurrence CTAs
#define FCTAS 148                // total fused CTAs

// fp8 scaling
#define SCALE_W 1024.0f
#define SCALE_H 256.0f
#define INV_SCALE 3.814697265625e-6f   // 1/(1024*256)

// work queue layout
#define GXT    800               // 50 m-tiles x 16 n-tiles
#define WCH    500               // wout fp8 conversion chunks (32768 elems each)
#define Q_WOUT GXT               // 800
#define Q_LOG  (GXT + WCH)       // 1300
#define QTOT   (Q_LOG + NTILES_L)

// ---------------- static scratch ----------------
__device__ float g_gx[(size_t)GXROWS * G4];
__device__ __nv_bfloat16 g_x_b[(size_t)XROWS_PAD * HID];
__device__ __nv_bfloat16 g_wih_b[2][(size_t)G4 * HID];
__device__ __half g_hs[2][BATCH * HID];
__device__ __nv_bfloat16 g_hall_b[(size_t)DROWS * HID];          // for combine_loss
__device__ unsigned char g_hall_f8[(size_t)DROWS_PAD * HID];     // fp8, pad rows stay zero
__device__ unsigned char g_wout_f8[(size_t)VOCAB * HID];         // fp8
__device__ float g_pmax[(size_t)DROWS * VT2];
__device__ float g_psum[(size_t)DROWS * VT2];
__device__ float g_losses[DROWS];
__device__ volatile int g_arrivev[PCTAS];
__device__ volatile int g_genv;
__device__ volatile int g_gx_donev[50];
__device__ volatile int g_wout_donev;
__device__ unsigned g_tile;

// ---------------- helpers ----------------
__device__ __forceinline__ uint32_t smem_u32(const void* p) {
    uint32_t a;
    asm("{ .reg .u64 t; cvta.to.shared.u64 t, %1; cvt.u32.u64 %0, t; }" : "=r"(a) : "l"(p));
    return a;
}
__device__ __forceinline__ void ldsm_x4(uint32_t* r, uint32_t addr) {
    asm volatile("ldmatrix.sync.aligned.m8n8.x4.shared.b16 {%0,%1,%2,%3}, [%4];"
        : "=r"(r[0]), "=r"(r[1]), "=r"(r[2]), "=r"(r[3]) : "r"(addr));
}
__device__ __forceinline__ void ldsm_x4_trans(uint32_t* r, uint32_t addr) {
    asm volatile("ldmatrix.sync.aligned.m8n8.x4.trans.shared.b16 {%0,%1,%2,%3}, [%4];"
        : "=r"(r[0]), "=r"(r[1]), "=r"(r[2]), "=r"(r[3]) : "r"(addr));
}
__device__ __forceinline__ void mma_bf16(float* c, const uint32_t* a, const uint32_t* b) {
    asm volatile("mma.sync.aligned.m16n8k16.row.col.f32.bf16.bf16.f32 "
        "{%0,%1,%2,%3}, {%4,%5,%6,%7}, {%8,%9}, {%0,%1,%2,%3};"
        : "+f"(c[0]), "+f"(c[1]), "+f"(c[2]), "+f"(c[3])
        : "r"(a[0]), "r"(a[1]), "r"(a[2]), "r"(a[3]), "r"(b[0]), "r"(b[1]));
}
__device__ __forceinline__ void mma_f16(float* c, const uint32_t* a, const uint32_t* b) {
    asm volatile("mma.sync.aligned.m16n8k16.row.col.f32.f16.f16.f32 "
        "{%0,%1,%2,%3}, {%4,%5,%6,%7}, {%8,%9}, {%0,%1,%2,%3};"
        : "+f"(c[0]), "+f"(c[1]), "+f"(c[2]), "+f"(c[3])
        : "r"(a[0]), "r"(a[1]), "r"(a[2]), "r"(a[3]), "r"(b[0]), "r"(b[1]));
}
__device__ __forceinline__ void mma_fp8(float* c, const uint32_t* a, const uint32_t* b) {
    asm volatile("mma.sync.aligned.m16n8k32.row.col.f32.e4m3.e4m3.f32 "
        "{%0,%1,%2,%3}, {%4,%5,%6,%7}, {%8,%9}, {%0,%1,%2,%3};"
        : "+f"(c[0]), "+f"(c[1]), "+f"(c[2]), "+f"(c[3])
        : "r"(a[0]), "r"(a[1]), "r"(a[2]), "r"(a[3]), "r"(b[0]), "r"(b[1]));
}
__device__ __forceinline__ void cp16(uint32_t sdst, const void* gsrc) {
    asm volatile("cp.async.cg.shared.global [%0], [%1], 16;" :: "r"(sdst), "l"(gsrc) : "memory");
}
#define CP_COMMIT() asm volatile("cp.async.commit_group;" ::: "memory")
#define CP_WAIT1()  asm volatile("cp.async.wait_group 1;" ::: "memory")
#define CP_WAIT0()  asm volatile("cp.async.wait_group 0;" ::: "memory")

__device__ __forceinline__ float sigmoidf_(float x) { return 1.0f / (1.0f + __expf(-x)); }
__device__ __forceinline__ float fexp(float x) {
    x = fmaxf(x, -87.0f);
    float y = x * 1.44269504088896f;
    float r = rintf(y);
    float f = (y - r) * 0.693147180559945f;
    float p = 1.0f + f * (1.0f + f * (0.5f + f * (0.16666667f + f * (0.041666667f + f * 0.0083333333f))));
    return __int_as_float(((int)r + 127) << 23) * p;
}

// ---------------- init ----------------
__global__ void init_kernel() {
    int i = blockIdx.x * blockDim.x + threadIdx.x;
    if (i < 2 * BATCH * HID / 2) ((uint32_t*)g_hs)[i] = 0u;
    if (i < PCTAS) g_arrivev[i] = 0;
    if (i < 50) g_gx_donev[i] = 0;
    if (i == 0) { g_genv = 0; g_tile = 0u; g_wout_donev = 0; }
}

// ---------------- W_ih conversions (needed before gx tiles) ----------------
__global__ void conv_wih(const float* __restrict__ wie, const float* __restrict__ wid) {
    int id = blockIdx.x >> 10;
    size_t i = ((size_t)(blockIdx.x & 1023) * 256 + threadIdx.x) * 4;
    const float* src = id ? wid : wie;
    float4 v = *(const float4*)&src[i];
    __nv_bfloat162 a = __floats2bfloat162_rn(v.x, v.y);
    __nv_bfloat162 b = __floats2bfloat162_rn(v.z, v.w);
    __nv_bfloat16* dst = g_wih_b[id];
    *(uint32_t*)&dst[i]     = *(uint32_t*)&a;
    *(uint32_t*)&dst[i + 2] = *(uint32_t*)&b;
}

// ---------------- gather emb rows -> bf16 x matrix ----------------
__global__ void prep_x(const int* __restrict__ inl, const int* __restrict__ tgl,
                       const float* __restrict__ embi, const float* __restrict__ embt) {
    int row = blockIdx.x;
    int k = threadIdx.x * 8;
    int tok; const float* e;
    if (row < SRC * BATCH)       { tok = inl[row]; e = embi; }
    else if (row < GXROWS)       { tok = tgl[row - SRC * BATCH]; e = embt; }
    else                         { tok = 0; e = embi; }
    const float4* s = (const float4*)(e + (size_t)tok * HID + k);
    float4 v0 = s[0], v1 = s[1];
    __nv_bfloat162 p0 = __floats2bfloat162_rn(v0.x, v0.y);
    __nv_bfloat162 p1 = __floats2bfloat162_rn(v0.z, v0.w);
    __nv_bfloat162 p2 = __floats2bfloat162_rn(v1.x, v1.y);
    __nv_bfloat162 p3 = __floats2bfloat162_rn(v1.z, v1.w);
    uint4 o = make_uint4(*(uint32_t*)&p0, *(uint32_t*)&p1, *(uint32_t*)&p2, *(uint32_t*)&p3);
    *(uint4*)&g_x_b[(size_t)row * HID + k] = o;
}

// ================= fused persistent kernel =================
#define PS_WS 0
#define PS_AS 65536
#define PS_GX 131072
#define PS_DS 147456
#define PS_CS 165888
#define PS_SMEM 167936

#define LGB_STG   49152
#define LGB_BIAS  147456
#define LGB_PM    148480
#define LGB_PSUM  150528
#define FS_SLOT   152576
#define FS_SMEM   PS_SMEM

// ---- recurrence body (CTAs 0..63) ----
__device__ void lstm_recur(char* sm, const float* __restrict__ whe, const float* __restrict__ whd) {
    const uint32_t smb = smem_u32(sm);
    float* gxs = (float*)(sm + PS_GX);
    float* Ds0 = (float*)(sm + PS_DS);
    float* Ds1 = (float*)(sm + PS_DS + 9216);
    float* cs  = (float*)(sm + PS_CS);
    const int tid = threadIdx.x;
    const int l = tid & 31;
    const int w = tid >> 5;
    const int wg = w >> 3;
    const int wr = w & 3;
    const int wc = (w >> 2) & 1;
    const int bid = blockIdx.x;
    const int j0 = bid * 8;

    // stage Whh (inline fp32 -> fp16 conversion): 2 sides x 8 kc x 32 rows x 128B
    for (int u = tid; u < 8192; u += 512) {
        int sd = u >> 12;
        int rem = u & 4095;
        int kcu = rem >> 8;
        int r2 = rem & 255;
        int rw = r2 >> 3;
        int k8 = (r2 & 7) * 8;
        int grow = (rw >> 3) * HID + j0 + (rw & 7);
        const float* wsrc = (sd ? whd : whe) + (size_t)grow * HID + kcu * 64 + k8;
        float4 v0 = *(const float4*)wsrc;
        float4 v1 = *(const float4*)(wsrc + 4);
        __half2 h0 = __floats2half2_rn(v0.x, v0.y);
        __half2 h1 = __floats2half2_rn(v0.z, v0.w);
        __half2 h2 = __floats2half2_rn(v1.x, v1.y);
        __half2 h3 = __floats2half2_rn(v1.z, v1.w);
        uint4 o = make_uint4(*(uint32_t*)&h0, *(uint32_t*)&h1, *(uint32_t*)&h2, *(uint32_t*)&h3);
        uint32_t so = (uint32_t)(rw * 128 + ((k8 * 2) ^ ((rw & 7) << 4)));
        *(uint4*)(sm + PS_WS + sd * 32768 + kcu * 4096 + so) = o;
    }
    cs[tid] = 0.0f;

    const int a_row = wr * 16 + (l & 7) + ((l & 8) ? 8 : 0);
    const int a_k8  = (l & 16) ? 8 : 0;
    const int b4_n  = (l & 7) + ((l & 16) ? 8 : 0);
    const int b4_k8 = (l & 8) ? 8 : 0;
    const int cb = tid >> 3;
    const int cjj = tid & 7;
    const int gx_b = tid >> 3;
    const int gx_g = (tid & 7) >> 1;
    const int gx_h = tid & 1;

    // gate on gx m-tile 0 (produced by worker CTAs)
    if (tid == 0) { while (g_gx_donev[0] < 16) __nanosleep(64); __threadfence(); }
    __syncthreads();

    cp16(smb + PS_GX + (uint32_t)(gx_b * 128 + gx_g * 32 + gx_h * 16),
         &g_gx[(size_t)gx_b * G4 + gx_g * 512 + j0 + gx_h * 4]);
    CP_COMMIT();

    for (int t = 0; t < NSTEP; ++t) {
        const int p = t & 1;
        const uint32_t wbase = smb + PS_WS + ((t < SRC) ? 0 : 32768) + wg * 4 * 4096;
        const __half* hsrc = g_hs[p];

#pragma unroll
        for (int i = 0; i < 8; ++i) {
            int u = tid + i * 512;
            int kc = u >> 9;
            int v2 = u & 511;
            int row = v2 >> 3;
            int k8 = (v2 & 7) * 8;
            uint32_t so = (uint32_t)(kc * 8192 + row * 128 + ((k8 * 2) ^ ((row & 7) << 4)));
            cp16(smb + PS_AS + so, &hsrc[(size_t)row * HID + kc * 64 + k8]);
        }
        CP_COMMIT();
        CP_WAIT0();
        __syncthreads();

        float acc[2][4];
#pragma unroll
        for (int j = 0; j < 2; ++j)
#pragma unroll
            for (int q = 0; q < 4; ++q) acc[j][q] = 0.0f;

#pragma unroll
        for (int kq = 0; kq < 4; ++kq) {
            const int kc = wg * 4 + kq;
#pragma unroll
            for (int ks = 0; ks < 4; ++ks) {
                uint32_t a[4];
                int ak = ks * 16 + a_k8;
                ldsm_x4(a, smb + PS_AS + kc * 8192 + a_row * 128 + ((ak * 2) ^ ((a_row & 7) << 4)));
                int bn = wc * 16 + b4_n;
                int bk = ks * 16 + b4_k8;
                uint32_t b[4];
                ldsm_x4_trans(b, wbase + kq * 4096 + bn * 128 + ((bk * 2) ^ ((bn & 7) << 4)));
                mma_f16(acc[0], a, b);
                mma_f16(acc[1], a, b + 2);
            }
        }

        float* Dsw = wg ? Ds1 : Ds0;
#pragma unroll
        for (int j = 0; j < 2; ++j) {
            int row = wr * 16 + (l >> 2);
            int col = wc * 16 + j * 8 + (l & 3) * 2;
            Dsw[row * 36 + col]           = acc[j][0];
            Dsw[row * 36 + col + 1]       = acc[j][1];
            Dsw[(row + 8) * 36 + col]     = acc[j][2];
            Dsw[(row + 8) * 36 + col + 1] = acc[j][3];
        }
        __syncthreads();

        {
            const float* gxb = gxs + (t & 1) * 2048;
            float gate[4];
#pragma unroll
            for (int g = 0; g < 4; ++g)
                gate[g] = Ds0[cb * 36 + g * 8 + cjj] + Ds1[cb * 36 + g * 8 + cjj]
                        + gxb[cb * 32 + g * 8 + cjj];
            float cc = cs[tid];
            float cn = sigmoidf_(gate[1]) * cc + sigmoidf_(gate[0]) * tanhf(gate[2]);
            float hn = sigmoidf_(gate[3]) * tanhf(cn);
            cs[tid] = cn;
            g_hs[p ^ 1][(size_t)cb * HID + j0 + cjj] = __float2half(hn);
            if (t >= SRC) {
                size_t dr = (size_t)((t - SRC) * BATCH + cb) * HID + j0 + cjj;
                g_hall_b[dr] = __float2bfloat16(hn);
                g_hall_f8[dr] = __nv_cvt_float_to_fp8(hn * SCALE_H, __NV_SATFINITE, __NV_E4M3);
            }
        }

        // ---- distributed grid barrier + gx(t+1) readiness gate ----
        __syncthreads();
        if (tid == 0) { __threadfence(); g_arrivev[bid] = t + 1; }
        if (tid < PCTAS) { while (g_arrivev[tid] < t + 1) {} }
        if (tid == 0 && t + 1 < NSTEP) {
            int mn = (t + 1) >> 1;
            while (g_gx_donev[mn] < 16) __nanosleep(32);
            __threadfence();
        }
        if (bid == 0 && tid == 0) { g_genv = t + 1; }
        __syncthreads();

        if (t + 1 < NSTEP) {
            cp16(smb + PS_GX + (uint32_t)(((t + 1) & 1) * 8192 + gx_b * 128 + gx_g * 32 + gx_h * 16),
                 &g_gx[(size_t)((t + 1) * BATCH + gx_b) * G4 + gx_g * 512 + j0 + gx_h * 4]);
            CP_COMMIT();
        }
    }
}

// ---- one gx tile: 128m x 128n GEMM (bf16 HMMA) -> g_gx + bias ----
__device__ void gx_tile(char* sm2, int mt, int nt,
                        const float* __restrict__ bihe, const float* __restrict__ bhhe,
                        const float* __restrict__ bihd, const float* __restrict__ bhhd) {
    const uint32_t sbase = smem_u32(sm2);
    const int tid = threadIdx.x;
    const int l = tid & 31;
    const int w = tid >> 5;
    const int wr = w & 3;
    const int wc = w >> 2;
    const int m0 = mt * 128;
    const int n0 = nt * 128;
    const int side = (m0 >= SRC * BATCH) ? 1 : 0;
    const __nv_bfloat16* Wih = g_wih_b[side];

    float* bias_s = (float*)(sm2 + LGB_BIAS);
    if (tid < 128) {
        const float* b1 = side ? bihd : bihe;
        const float* b2 = side ? bhhd : bhhe;
        bias_s[tid] = b1[n0 + tid] + b2[n0 + tid];
    }

    float acc[2][4][4];
#pragma unroll
    for (int i = 0; i < 2; ++i)
#pragma unroll
        for (int j = 0; j < 4; ++j)
#pragma unroll
            for (int q = 0; q < 4; ++q) acc[i][j][q] = 0.0f;

    const int a_row = wr * 32 + (l & 7) + ((l & 8) ? 8 : 0);
    const int a_k8  = (l & 16) ? 8 : 0;
    const int b4_n  = (l & 7) + ((l & 16) ? 8 : 0);
    const int b4_k8 = (l & 8) ? 8 : 0;

#define GXT_STAGE_LD(kb, s) do {                                                      \
        uint32_t base = sbase + (s) * LGB_STG;                                        \
        _Pragma("unroll")                                                             \
        for (int i_ = 0; i_ < 2; ++i_) {                                              \
            int c_ = tid + i_ * 512;                                                  \
            int row_ = c_ >> 3;                                                       \
            int k8_ = (c_ & 7) * 8;                                                   \
            uint32_t so_ = (uint32_t)(row_ * 128 + ((k8_ * 2) ^ ((row_ & 7) << 4)));  \
            cp16(base + so_,         &g_x_b[(size_t)(m0 + row_) * HID + (kb) + k8_]); \
            cp16(base + 16384 + so_, &Wih[(size_t)(n0 + row_) * HID + (kb) + k8_]);   \
        }                                                                             \
        CP_COMMIT();                                                                  \
    } while (0)

    GXT_STAGE_LD(0, 0);
    GXT_STAGE_LD(64, 1);
    for (int c = 0; c < 8; ++c) {
        if (c < 7) { CP_WAIT1(); } else { CP_WAIT0(); }
        __syncthreads();
        if (c < 6) GXT_STAGE_LD((c + 2) * 64, (c + 2) % 3);
        const uint32_t aB = sbase + (c % 3) * LGB_STG;
        const uint32_t bB = aB + 16384;
#pragma unroll
        for (int ks = 0; ks < 4; ++ks) {
            uint32_t a[2][4];
#pragma unroll
            for (int i = 0; i < 2; ++i) {
                int ar = a_row + i * 16;
                int ak = ks * 16 + a_k8;
                ldsm_x4(a[i], aB + ar * 128 + ((ak * 2) ^ ((ar & 7) << 4)));
            }
#pragma unroll
            for (int j16 = 0; j16 < 2; ++j16) {
                int bn = wc * 32 + j16 * 16 + b4_n;
                int bk = ks * 16 + b4_k8;
                uint32_t b[4];
                ldsm_x4_trans(b, bB + bn * 128 + ((bk * 2) ^ ((bn & 7) << 4)));
                mma_bf16(acc[0][j16 * 2],     a[0], b);
                mma_bf16(acc[1][j16 * 2],     a[1], b);
                mma_bf16(acc[0][j16 * 2 + 1], a[0], b + 2);
                mma_bf16(acc[1][j16 * 2 + 1], a[1], b + 2);
            }
        }
    }

#pragma unroll
    for (int i = 0; i < 2; ++i)
#pragma unroll
        for (int j = 0; j < 4; ++j) {
            int row0 = m0 + wr * 32 + i * 16 + (l >> 2);
            int colL = wc * 32 + j * 8 + (l & 3) * 2;
            int col = n0 + colL;
            if (row0 < GXROWS) {
                float2 v0 = make_float2(acc[i][j][0] + bias_s[colL], acc[i][j][1] + bias_s[colL + 1]);
                *(float2*)&g_gx[(size_t)row0 * G4 + col] = v0;
            }
            int row1 = row0 + 8;
            if (row1 < GXROWS) {
                float2 v1 = make_float2(acc[i][j][2] + bias_s[colL], acc[i][j][3] + bias_s[colL + 1]);
                *(float2*)&g_gx[(size_t)row1 * G4 + col] = v1;
            }
        }
    __threadfence();
    __syncthreads();
    if (tid == 0) atomicAdd((int*)&g_gx_donev[mt], 1);
}

// ---- one wout fp8 conversion chunk (32768 elems) ----
__device__ void wout_chunk(int c, const float* __restrict__ W_out) {
    const int tid = threadIdx.x;
    size_t base4 = (size_t)c * 8192;           // float4 units
#pragma unroll
    for (int i = 0; i < 16; ++i) {
        size_t idx = base4 + tid + (size_t)i * 512;
        float4 v = ((const float4*)W_out)[idx];
        __nv_fp8x2_storage_t lo = __nv_cvt_float2_to_fp8x2(make_float2(v.x * SCALE_W, v.y * SCALE_W),
                                                           __NV_SATFINITE, __NV_E4M3);
        __nv_fp8x2_storage_t hi = __nv_cvt_float2_to_fp8x2(make_float2(v.z * SCALE_W, v.w * SCALE_W),
                                                           __NV_SATFINITE, __NV_E4M3);
        ((uint32_t*)g_wout_f8)[idx] = (uint32_t)lo | ((uint32_t)hi << 16);
    }
    __threadfence();
    __syncthreads();
    if (tid == 0) atomicAdd((int*)&g_wout_donev, 1);
}

// ---- one logits tile: 128m x 256n fp8 GEMM + fused LSE partials ----
__device__ void logits_tile(char* sm2, int m0, int ntile, const float* __restrict__ bout) {
    const uint32_t sbase = smem_u32(sm2);
    const int tid = threadIdx.x;
    const int l = tid & 31;
    const int w = tid >> 5;
    const int wr = w & 3;
    const int wc = w >> 2;
    const int n0 = ntile * 256;

    float* bias_s = (float*)(sm2 + LGB_BIAS);
    float* pm = (float*)(sm2 + LGB_PM);
    float* ps = (float*)(sm2 + LGB_PSUM);
    if (tid < 256) bias_s[tid] = bout[n0 + tid];

    float acc[2][8][4];
#pragma unroll
    for (int i = 0; i < 2; ++i)
#pragma unroll
        for (int j = 0; j < 8; ++j)
#pragma unroll
            for (int q = 0; q < 4; ++q) acc[i][j][q] = 0.0f;

    const int a_row = wr * 32 + (l & 7) + ((l & 8) ? 8 : 0);
    const int a_k8  = (l & 16) ? 8 : 0;
    const int b4_n  = (l & 7) + ((l & 16) ? 8 : 0);
    const int b4_k8 = (l & 8) ? 8 : 0;

    // fp8: rows are 512 bytes; chunk = 128 bytes/row (128 k-elems), 4 chunks total
#define LGF_STAGE_LD(kb, s) do {                                                      \
        uint32_t base = sbase + (s) * LGB_STG;                                        \
        _Pragma("unroll")                                                             \
        for (int i_ = 0; i_ < 2; ++i_) {                                              \
            int c_ = tid + i_ * 512;                                                  \
            int row_ = c_ >> 3;                                                       \
            int kb_ = (c_ & 7) * 16;                                                  \
            uint32_t so_ = (uint32_t)(row_ * 128 + (kb_ ^ ((row_ & 7) << 4)));        \
            cp16(base + so_, &g_hall_f8[(size_t)(m0 + row_) * HID + (kb) + kb_]);     \
        }                                                                             \
        _Pragma("unroll")                                                             \
        for (int i_ = 0; i_ < 4; ++i_) {                                              \
            int c_ = tid + i_ * 512;                                                  \
            int row_ = c_ >> 3;                                                       \
            int kb_ = (c_ & 7) * 16;                                                  \
            uint32_t so_ = (uint32_t)(row_ * 128 + (kb_ ^ ((row_ & 7) << 4)));        \
            cp16(base + 16384 + so_, &g_wout_f8[(size_t)(n0 + row_) * HID + (kb) + kb_]); \
        }                                                                             \
        CP_COMMIT();                                                                  \
    } while (0)

    LGF_STAGE_LD(0, 0);
    LGF_STAGE_LD(128, 1);
    for (int c = 0; c < 4; ++c) {
        if (c < 3) { CP_WAIT1(); } else { CP_WAIT0(); }
        __syncthreads();
        if (c < 2) LGF_STAGE_LD((c + 2) * 128, (c + 2) % 3);
        const uint32_t aB = sbase + (c % 3) * LGB_STG;
        const uint32_t bB = aB + 16384;
#pragma unroll
        for (int ks = 0; ks < 4; ++ks) {
            uint32_t a[2][4];
#pragma unroll
            for (int i = 0; i < 2; ++i) {
                int ar = a_row + i * 16;
                int ak = ks * 16 + a_k8;            // 16-bit units (= fp8 pairs)
                ldsm_x4(a[i], aB + ar * 128 + ((ak * 2) ^ ((ar & 7) << 4)));
            }
#pragma unroll
            for (int j16 = 0; j16 < 4; ++j16) {
                int bn = wc * 64 + j16 * 16 + b4_n;
                int bk = ks * 16 + b4_k8;
                uint32_t b[4];
                ldsm_x4_trans(b, bB + bn * 128 + ((bk * 2) ^ ((bn & 7) << 4)));
                mma_fp8(acc[0][j16 * 2],     a[0], b);
                mma_fp8(acc[1][j16 * 2],     a[1], b);
                mma_fp8(acc[0][j16 * 2 + 1], a[0], b + 2);
                mma_fp8(acc[1][j16 * 2 + 1], a[1], b + 2);
            }
        }
    }

#pragma unroll
    for (int i = 0; i < 2; ++i) {
#pragma unroll
        for (int half = 0; half < 2; ++half) {
            int row = wr * 32 + i * 16 + (l >> 2) + half * 8;
            float m = -INFINITY;
#pragma unroll
            for (int j = 0; j < 8; ++j) {
                int colL = wc * 64 + j * 8 + (l & 3) * 2;
                float v0 = acc[i][j][half * 2]     * INV_SCALE + bias_s[colL];
                float v1 = acc[i][j][half * 2 + 1] * INV_SCALE + bias_s[colL + 1];
                m = fmaxf(m, fmaxf(v0, v1));
            }
            float sx = 0.0f;
#pragma unroll
            for (int j = 0; j < 8; ++j) {
                int colL = wc * 64 + j * 8 + (l & 3) * 2;
                sx += fexp(acc[i][j][half * 2]     * INV_SCALE + bias_s[colL]     - m);
                sx += fexp(acc[i][j][half * 2 + 1] * INV_SCALE + bias_s[colL + 1] - m);
            }
#pragma unroll
            for (int d = 1; d < 4; d <<= 1) {
                float mo = __shfl_xor_sync(0xffffffffu, m, d);
                float so = __shfl_xor_sync(0xffffffffu, sx, d);
                float mm = fmaxf(m, mo);
                sx = sx * fexp(m - mm) + so * fexp(mo - mm);
                m = mm;
            }
            if ((l & 3) == 0) {
                pm[row * 4 + wc] = m;
                ps[row * 4 + wc] = sx;
            }
        }
    }
    __syncthreads();

    if (tid < 128) {
        float m = pm[tid * 4];
#pragma unroll
        for (int q = 1; q < 4; ++q) m = fmaxf(m, pm[tid * 4 + q]);
        float sx = 0.0f;
#pragma unroll
        for (int q = 0; q < 4; ++q) sx += ps[tid * 4 + q] * fexp(pm[tid * 4 + q] - m);
        int gr = m0 + tid;
        if (gr < DROWS) {
            g_pmax[(size_t)gr * VT2 + ntile] = m;
            g_psum[(size_t)gr * VT2 + ntile] = sx;
        }
    }
}

// ---- fused kernel ----
__global__ __launch_bounds__(512, 1) void fused_kernel(
    const float* __restrict__ bout, const float* __restrict__ W_out,
    const float* __restrict__ bihe, const float* __restrict__ bhhe,
    const float* __restrict__ bihd, const float* __restrict__ bhhd,
    const float* __restrict__ whe,  const float* __restrict__ whd) {
    extern __shared__ __align__(16) char sm[];
    const int tid = threadIdx.x;

    if (blockIdx.x < PCTAS) {
        lstm_recur(sm, whe, whd);
        __syncthreads();
    }

    // work queue: [0,800) gx tiles, [800,1300) wout chunks, [1300,4425) logits tiles
    int* slot = (int*)(sm + FS_SLOT);
    for (;;) {
        if (tid == 0) {
            int tile = (int)atomicAdd(&g_tile, 1u);
            *slot = tile;
            if (tile >= Q_LOG && tile < QTOT) {
                int lt = tile - Q_LOG;
                int m = lt / VT2;
                int ready = SRC + 2 * m + 2;
                if (ready > NSTEP) ready = NSTEP;
                while (g_wout_donev < WCH) __nanosleep(64);
                while (g_genv < ready) __nanosleep(64);
                __threadfence();
            }
        }
        __syncthreads();
        int tile = *slot;
        if (tile >= QTOT) break;
        if (tile < Q_WOUT) {
            gx_tile(sm, tile >> 4, tile & 15, bihe, bhhe, bihd, bhhd);
        } else if (tile < Q_LOG) {
            wout_chunk(tile - Q_WOUT, W_out);
        } else {
            int lt = tile - Q_LOG;
            logits_tile(sm, (lt / VT2) * 128, lt % VT2, bout);
        }
        __syncthreads();
    }
}

// ================= combine partials -> per-(d,b) loss =================
__global__ void combine_loss(const int* __restrict__ target_lines,
                             const float* __restrict__ bout,
                             const float* __restrict__ W_out) {
    __shared__ float sred[128];
    const int b = blockIdx.x;
    const int d = blockIdx.y;
    const int bs = d * BATCH + b;
    const int tid = threadIdx.x;

    float m = -INFINITY;
    for (int p = tid; p < VT2; p += 128) m = fmaxf(m, g_pmax[(size_t)bs * VT2 + p]);
    sred[tid] = m;
    __syncthreads();
    for (int s = 64; s > 0; s >>= 1) {
        if (tid < s) sred[tid] = fmaxf(sred[tid], sred[tid + s]);
        __syncthreads();
    }
    const float gmax = sred[0];
    __syncthreads();

    float sum = 0.0f;
    for (int p = tid; p < VT2; p += 128)
        sum += g_psum[(size_t)bs * VT2 + p] * __expf(g_pmax[(size_t)bs * VT2 + p] - gmax);
    sred[tid] = sum;
    __syncthreads();
    for (int s = 64; s > 0; s >>= 1) {
        if (tid < s) sred[tid] += sred[tid + s];
        __syncthreads();
    }
    const float gsum = sred[0];
    __syncthreads();

    const int nxt = target_lines[(d + 1) * BATCH + b];
    const __nv_bfloat16* hrow = &g_hall_b[(size_t)bs * HID];
    const float* wrow = &W_out[(size_t)nxt * HID];
    float ds = 0.0f;
#pragma unroll
    for (int q = 0; q < 4; ++q)
        ds += __bfloat162float(hrow[tid * 4 + q]) * wrow[tid * 4 + q];
    sred[tid] = ds;
    __syncthreads();
    for (int s = 64; s > 0; s >>= 1) {
        if (tid < s) sred[tid] += sred[tid + s];
        __syncthreads();
    }
    if (tid == 0)
        g_losses[bs] = -(sred[0] + bout[nxt] - gmax - logf(gsum));
}

// ---------------- final deterministic sum ----------------
__global__ void final_kernel(float* __restrict__ out) {
    __shared__ float sred[256];
    const int tid = threadIdx.x;
    float s = 0.0f;
    for (int i = tid; i < DROWS; i += 256) s += g_losses[i];
    sred[tid] = s;
    __syncthreads();
    for (int st = 128; st > 0; st >>= 1) {
        if (tid < st) sred[tid] += sred[tid + st];
        __syncthreads();
    }
    if (tid == 0) out[0] = sred[0] * (1.0f / (float)BATCH);
}

// ---------------- host ----------------
extern "C" void kernel_launch(void* const* d_in, const int* in_sizes, int n_in,
                              void* d_out, int out_size) {
    (void)in_sizes; (void)n_in; (void)out_size;
    const int*   input_lines  = (const int*)  d_in[0];
    const int*   target_lines = (const int*)  d_in[1];
    const float* emb_in       = (const float*)d_in[2];
    const float* emb_tgt      = (const float*)d_in[3];
    const float* W_ih_enc     = (const float*)d_in[4];
    const float* W_hh_enc     = (const float*)d_in[5];
    const float* b_ih_enc     = (const float*)d_in[6];
    const float* b_hh_enc     = (const float*)d_in[7];
    const float* W_ih_dec     = (const float*)d_in[8];
    const float* W_hh_dec     = (const float*)d_in[9];
    const float* b_ih_dec     = (const float*)d_in[10];
    const float* b_hh_dec     = (const float*)d_in[11];
    const float* W_out        = (const float*)d_in[12];
    const float* b_out        = (const float*)d_in[13];
    float* out = (float*)d_out;

    cudaFuncSetAttribute(fused_kernel, cudaFuncAttributeMaxDynamicSharedMemorySize, FS_SMEM);

    init_kernel<<<256, 256>>>();
    conv_wih<<<2048, 256>>>(W_ih_enc, W_ih_dec);
    prep_x<<<XROWS_PAD, 64>>>(input_lines, target_lines, emb_in, emb_tgt);

    fused_kernel<<<FCTAS, 512, FS_SMEM>>>(b_out, W_out,
                                          b_ih_enc, b_hh_enc, b_ih_dec, b_hh_dec,
                                          W_hh_enc, W_hh_dec);

    combine_loss<<<dim3(BATCH, TGT), 128>>>(target_lines, b_out, W_out);
    final_kernel<<<1, 256>>>(out);
}

// round 13
// speedup vs baseline: 1.5607x; 1.5607x over previous
#include <cuda_runtime.h>
#include <cuda_bf16.h>
#include <cuda_fp16.h>
#include <math.h>
#include <stdint.h>

#define HID   512
#define G4    2048
#define BATCH 64
#define VOCAB 32000
#define SRC   50
#define TGT   49
#define NSTEP (SRC + TGT)

#define VT2    125               // 32000 / 256
#define MT2    25                // 3200 / 128
#define NTILES (MT2 * VT2)       // 3125 logits tiles
#define DROWS  (TGT * BATCH)     // 3136 decode rows
#define DROWS_PAD 3200
#define GXROWS (NSTEP * BATCH)   // 6336
#define XROWS_PAD 6400
#define PCTAS 64                 // recurrence CTAs
#define FCTAS 148                // total fused CTAs

// ---------------- static scratch ----------------
__device__ float g_gx[(size_t)GXROWS * G4];
__device__ __nv_bfloat16 g_x_b[(size_t)XROWS_PAD * HID];
__device__ __nv_bfloat16 g_wih_b[2][(size_t)G4 * HID];
__device__ __half g_whh_h[2][(size_t)G4 * HID];
__device__ __half g_hs[2][BATCH * HID];
__device__ __nv_bfloat16 g_hall_b[(size_t)DROWS_PAD * HID];  // pad rows stay zero
__device__ __nv_bfloat16 g_wout_b[(size_t)VOCAB * HID];
__device__ float g_pmax[(size_t)DROWS * VT2];
__device__ float g_psum[(size_t)DROWS * VT2];
__device__ float g_losses[DROWS];
__device__ volatile int g_arrivev[PCTAS];
__device__ volatile int g_genv;
__device__ unsigned g_tile;

// ---------------- helpers ----------------
__device__ __forceinline__ uint32_t smem_u32(const void* p) {
    uint32_t a;
    asm("{ .reg .u64 t; cvta.to.shared.u64 t, %1; cvt.u32.u64 %0, t; }" : "=r"(a) : "l"(p));
    return a;
}
__device__ __forceinline__ void ldsm_x4(uint32_t* r, uint32_t addr) {
    asm volatile("ldmatrix.sync.aligned.m8n8.x4.shared.b16 {%0,%1,%2,%3}, [%4];"
        : "=r"(r[0]), "=r"(r[1]), "=r"(r[2]), "=r"(r[3]) : "r"(addr));
}
__device__ __forceinline__ void ldsm_x4_trans(uint32_t* r, uint32_t addr) {
    asm volatile("ldmatrix.sync.aligned.m8n8.x4.trans.shared.b16 {%0,%1,%2,%3}, [%4];"
        : "=r"(r[0]), "=r"(r[1]), "=r"(r[2]), "=r"(r[3]) : "r"(addr));
}
__device__ __forceinline__ void mma_bf16(float* c, const uint32_t* a, const uint32_t* b) {
    asm volatile("mma.sync.aligned.m16n8k16.row.col.f32.bf16.bf16.f32 "
        "{%0,%1,%2,%3}, {%4,%5,%6,%7}, {%8,%9}, {%0,%1,%2,%3};"
        : "+f"(c[0]), "+f"(c[1]), "+f"(c[2]), "+f"(c[3])
        : "r"(a[0]), "r"(a[1]), "r"(a[2]), "r"(a[3]), "r"(b[0]), "r"(b[1]));
}
__device__ __forceinline__ void mma_f16(float* c, const uint32_t* a, const uint32_t* b) {
    asm volatile("mma.sync.aligned.m16n8k16.row.col.f32.f16.f16.f32 "
        "{%0,%1,%2,%3}, {%4,%5,%6,%7}, {%8,%9}, {%0,%1,%2,%3};"
        : "+f"(c[0]), "+f"(c[1]), "+f"(c[2]), "+f"(c[3])
        : "r"(a[0]), "r"(a[1]), "r"(a[2]), "r"(a[3]), "r"(b[0]), "r"(b[1]));
}
__device__ __forceinline__ void cp16(uint32_t sdst, const void* gsrc) {
    asm volatile("cp.async.cg.shared.global [%0], [%1], 16;" :: "r"(sdst), "l"(gsrc) : "memory");
}
#define CP_COMMIT() asm volatile("cp.async.commit_group;" ::: "memory")
#define CP_WAIT1()  asm volatile("cp.async.wait_group 1;" ::: "memory")
#define CP_WAIT0()  asm volatile("cp.async.wait_group 0;" ::: "memory")

__device__ __forceinline__ float sigmoidf_(float x) { return 1.0f / (1.0f + __expf(-x)); }
__device__ __forceinline__ float fexp(float x) {
    x = fmaxf(x, -87.0f);
    float y = x * 1.44269504088896f;
    float r = rintf(y);
    float f = (y - r) * 0.693147180559945f;
    float p = 1.0f + f * (1.0f + f * (0.5f + f * (0.16666667f + f * (0.041666667f + f * 0.0083333333f))));
    return __int_as_float(((int)r + 127) << 23) * p;
}

// ---------------- init ----------------
__global__ void init_kernel() {
    int i = blockIdx.x * blockDim.x + threadIdx.x;
    if (i < 2 * BATCH * HID / 2) ((uint32_t*)g_hs)[i] = 0u;
    if (i < PCTAS) g_arrivev[i] = 0;
    if (i == 0) { g_genv = 0; g_tile = 0u; }
}

// ---------------- merged small-weight conversions ----------------
__global__ void conv_weights(const float* __restrict__ wie, const float* __restrict__ wid,
                             const float* __restrict__ whe, const float* __restrict__ whd) {
    int id = blockIdx.x >> 10;
    size_t i = ((size_t)(blockIdx.x & 1023) * 256 + threadIdx.x) * 4;
    const float* src = (id == 0) ? wie : (id == 1) ? wid : (id == 2) ? whe : whd;
    float4 v = *(const float4*)&src[i];
    if (id < 2) {
        __nv_bfloat162 a = __floats2bfloat162_rn(v.x, v.y);
        __nv_bfloat162 b = __floats2bfloat162_rn(v.z, v.w);
        __nv_bfloat16* dst = g_wih_b[id];
        *(uint32_t*)&dst[i]     = *(uint32_t*)&a;
        *(uint32_t*)&dst[i + 2] = *(uint32_t*)&b;
    } else {
        __half2 a = __floats2half2_rn(v.x, v.y);
        __half2 b = __floats2half2_rn(v.z, v.w);
        __half* dst = g_whh_h[id - 2];
        *(uint32_t*)&dst[i]     = *(uint32_t*)&a;
        *(uint32_t*)&dst[i + 2] = *(uint32_t*)&b;
    }
}
__global__ void conv_wout(const float* __restrict__ src) {
    size_t i = ((size_t)blockIdx.x * 256 + threadIdx.x) * 4;
    float4 v = *(const float4*)&src[i];
    __nv_bfloat162 a = __floats2bfloat162_rn(v.x, v.y);
    __nv_bfloat162 b = __floats2bfloat162_rn(v.z, v.w);
    *(uint32_t*)&g_wout_b[i]     = *(uint32_t*)&a;
    *(uint32_t*)&g_wout_b[i + 2] = *(uint32_t*)&b;
}

// ---------------- gather emb rows -> bf16 x matrix ----------------
__global__ void prep_x(const int* __restrict__ inl, const int* __restrict__ tgl,
                       const float* __restrict__ embi, const float* __restrict__ embt) {
    int row = blockIdx.x;
    int k = threadIdx.x * 8;
    int tok; const float* e;
    if (row < SRC * BATCH)       { tok = inl[row]; e = embi; }
    else if (row < GXROWS)       { tok = tgl[row - SRC * BATCH]; e = embt; }
    else                         { tok = 0; e = embi; }
    const float4* s = (const float4*)(e + (size_t)tok * HID + k);
    float4 v0 = s[0], v1 = s[1];
    __nv_bfloat162 p0 = __floats2bfloat162_rn(v0.x, v0.y);
    __nv_bfloat162 p1 = __floats2bfloat162_rn(v0.z, v0.w);
    __nv_bfloat162 p2 = __floats2bfloat162_rn(v1.x, v1.y);
    __nv_bfloat162 p3 = __floats2bfloat162_rn(v1.z, v1.w);
    uint4 o = make_uint4(*(uint32_t*)&p0, *(uint32_t*)&p1, *(uint32_t*)&p2, *(uint32_t*)&p3);
    *(uint4*)&g_x_b[(size_t)row * HID + k] = o;
}

// ================= gx GEMM (bf16 HMMA, cp.async 3-stage, 1 sync/chunk) =================
#define GX_SMEM 98816            // 3 x 32768 + 512 bias

__global__ __launch_bounds__(256) void gx_mma(const float* __restrict__ bihe, const float* __restrict__ bhhe,
                                              const float* __restrict__ bihd, const float* __restrict__ bhhd) {
    extern __shared__ __align__(16) char sm[];
    const uint32_t sb = smem_u32(sm);
    const int tid = threadIdx.x;
    const int l = tid & 31;
    const int w = tid >> 5;
    const int wr = w & 3;
    const int wc = w >> 2;
    const int n0 = blockIdx.x * 128;
    const int m0 = blockIdx.y * 128;
    const int side = (m0 >= SRC * BATCH) ? 1 : 0;
    const __nv_bfloat16* Wih = g_wih_b[side];
    float* bs = (float*)(sm + 98304);

    if (tid < 128) {
        const float* b1 = side ? bihd : bihe;
        const float* b2 = side ? bhhd : bhhe;
        bs[tid] = b1[n0 + tid] + b2[n0 + tid];
    }

    float acc[2][8][4];
#pragma unroll
    for (int i = 0; i < 2; ++i)
#pragma unroll
        for (int j = 0; j < 8; ++j)
#pragma unroll
            for (int q = 0; q < 4; ++q) acc[i][j][q] = 0.0f;

    const int a_row = wr * 32 + (l & 7) + ((l & 8) ? 8 : 0);
    const int a_k8  = (l & 16) ? 8 : 0;
    const int b4_n  = (l & 7) + ((l & 16) ? 8 : 0);
    const int b4_k8 = (l & 8) ? 8 : 0;

#define GX_STAGE(kb, s) do {                                                          \
        uint32_t base = sb + (s) * 32768;                                             \
        _Pragma("unroll")                                                             \
        for (int i_ = 0; i_ < 4; ++i_) {                                              \
            int c_ = tid + i_ * 256;                                                  \
            int row_ = c_ >> 3;                                                       \
            int k8_ = (c_ & 7) * 8;                                                   \
            uint32_t so_ = (uint32_t)(row_ * 128 + ((k8_ * 2) ^ ((row_ & 7) << 4)));  \
            cp16(base + so_,         &g_x_b[(size_t)(m0 + row_) * HID + (kb) + k8_]); \
            cp16(base + 16384 + so_, &Wih[(size_t)(n0 + row_) * HID + (kb) + k8_]);   \
        }                                                                             \
        CP_COMMIT();                                                                  \
    } while (0)

    GX_STAGE(0, 0);
    GX_STAGE(64, 1);
    for (int c = 0; c < 8; ++c) {
        if (c < 7) { CP_WAIT1(); } else { CP_WAIT0(); }
        __syncthreads();
        if (c < 6) GX_STAGE((c + 2) * 64, (c + 2) % 3);
        const uint32_t aB = sb + (c % 3) * 32768;
        const uint32_t bB = aB + 16384;
#pragma unroll
        for (int ks = 0; ks < 4; ++ks) {
            uint32_t a[2][4];
#pragma unroll
            for (int i = 0; i < 2; ++i) {
                int ar = a_row + i * 16;
                int ak = ks * 16 + a_k8;
                ldsm_x4(a[i], aB + ar * 128 + ((ak * 2) ^ ((ar & 7) << 4)));
            }
#pragma unroll
            for (int j16 = 0; j16 < 4; ++j16) {
                int bn = wc * 64 + j16 * 16 + b4_n;
                int bk = ks * 16 + b4_k8;
                uint32_t b[4];
                ldsm_x4_trans(b, bB + bn * 128 + ((bk * 2) ^ ((bn & 7) << 4)));
                mma_bf16(acc[0][j16 * 2],     a[0], b);
                mma_bf16(acc[1][j16 * 2],     a[1], b);
                mma_bf16(acc[0][j16 * 2 + 1], a[0], b + 2);
                mma_bf16(acc[1][j16 * 2 + 1], a[1], b + 2);
            }
        }
    }

#pragma unroll
    for (int i = 0; i < 2; ++i)
#pragma unroll
        for (int j = 0; j < 8; ++j) {
            int row0 = m0 + wr * 32 + i * 16 + (l >> 2);
            int colL = wc * 64 + j * 8 + (l & 3) * 2;
            int col = n0 + colL;
            if (row0 < GXROWS) {
                float2 v0 = make_float2(acc[i][j][0] + bs[colL], acc[i][j][1] + bs[colL + 1]);
                *(float2*)&g_gx[(size_t)row0 * G4 + col] = v0;
            }
            int row1 = row0 + 8;
            if (row1 < GXROWS) {
                float2 v1 = make_float2(acc[i][j][2] + bs[colL], acc[i][j][3] + bs[colL + 1]);
                *(float2*)&g_gx[(size_t)row1 * G4 + col] = v1;
            }
        }
}

// ================= fused persistent kernel: LSTM recurrence + logits workers =================
#define PS_WS 0
#define PS_AS 65536
#define PS_GX 131072
#define PS_DS 147456
#define PS_CS 165888
#define PS_SMEM 167936

#define LGB_STG   49152
#define LGB_BIAS  147456
#define LGB_PM    148480
#define LGB_PSUM  150528
#define FS_SLOT   152576
#define FS_SMEM   PS_SMEM

// ---- recurrence body (CTAs 0..63) ----
__device__ void lstm_recur(char* sm) {
    const uint32_t smb = smem_u32(sm);
    float* gxs = (float*)(sm + PS_GX);
    float* Ds0 = (float*)(sm + PS_DS);
    float* Ds1 = (float*)(sm + PS_DS + 9216);
    float* cs  = (float*)(sm + PS_CS);
    const int tid = threadIdx.x;
    const int l = tid & 31;
    const int w = tid >> 5;
    const int wg = w >> 3;
    const int wr = w & 3;
    const int wc = (w >> 2) & 1;
    const int bid = blockIdx.x;
    const int j0 = bid * 8;

    for (int u = tid; u < 8192; u += 512) {
        int sd = u >> 12;
        int rem = u & 4095;
        int kcu = rem >> 8;
        int r2 = rem & 255;
        int rw = r2 >> 3;
        int k8 = (r2 & 7) * 8;
        int grow = (rw >> 3) * HID + j0 + (rw & 7);
        uint4 v = *(const uint4*)&g_whh_h[sd][(size_t)grow * HID + kcu * 64 + k8];
        uint32_t so = (uint32_t)(rw * 128 + ((k8 * 2) ^ ((rw & 7) << 4)));
        *(uint4*)(sm + PS_WS + sd * 32768 + kcu * 4096 + so) = v;
    }
    cs[tid] = 0.0f;
    __syncthreads();

    const int a_row = wr * 16 + (l & 7) + ((l & 8) ? 8 : 0);
    const int a_k8  = (l & 16) ? 8 : 0;
    const int b4_n  = (l & 7) + ((l & 16) ? 8 : 0);
    const int b4_k8 = (l & 8) ? 8 : 0;
    const int cb = tid >> 3;
    const int cjj = tid & 7;
    const int gx_b = tid >> 3;
    const int gx_g = (tid & 7) >> 1;
    const int gx_h = tid & 1;

    cp16(smb + PS_GX + (uint32_t)(gx_b * 128 + gx_g * 32 + gx_h * 16),
         &g_gx[(size_t)gx_b * G4 + gx_g * 512 + j0 + gx_h * 4]);
    CP_COMMIT();

    for (int t = 0; t < NSTEP; ++t) {
        const int p = t & 1;
        const uint32_t wbase = smb + PS_WS + ((t < SRC) ? 0 : 32768) + wg * 4 * 4096;
        const __half* hsrc = g_hs[p];

#pragma unroll
        for (int i = 0; i < 8; ++i) {
            int u = tid + i * 512;
            int kc = u >> 9;
            int v2 = u & 511;
            int row = v2 >> 3;
            int k8 = (v2 & 7) * 8;
            uint32_t so = (uint32_t)(kc * 8192 + row * 128 + ((k8 * 2) ^ ((row & 7) << 4)));
            cp16(smb + PS_AS + so, &hsrc[(size_t)row * HID + kc * 64 + k8]);
        }
        CP_COMMIT();
        CP_WAIT0();
        __syncthreads();

        float acc[2][4];
#pragma unroll
        for (int j = 0; j < 2; ++j)
#pragma unroll
            for (int q = 0; q < 4; ++q) acc[j][q] = 0.0f;

#pragma unroll
        for (int kq = 0; kq < 4; ++kq) {
            const int kc = wg * 4 + kq;
#pragma unroll
            for (int ks = 0; ks < 4; ++ks) {
                uint32_t a[4];
                int ak = ks * 16 + a_k8;
                ldsm_x4(a, smb + PS_AS + kc * 8192 + a_row * 128 + ((ak * 2) ^ ((a_row & 7) << 4)));
                int bn = wc * 16 + b4_n;
                int bk = ks * 16 + b4_k8;
                uint32_t b[4];
                ldsm_x4_trans(b, wbase + kq * 4096 + bn * 128 + ((bk * 2) ^ ((bn & 7) << 4)));
                mma_f16(acc[0], a, b);
                mma_f16(acc[1], a, b + 2);
            }
        }

        float* Dsw = wg ? Ds1 : Ds0;
#pragma unroll
        for (int j = 0; j < 2; ++j) {
            int row = wr * 16 + (l >> 2);
            int col = wc * 16 + j * 8 + (l & 3) * 2;
            Dsw[row * 36 + col]           = acc[j][0];
            Dsw[row * 36 + col + 1]       = acc[j][1];
            Dsw[(row + 8) * 36 + col]     = acc[j][2];
            Dsw[(row + 8) * 36 + col + 1] = acc[j][3];
        }
        __syncthreads();

        {
            const float* gxb = gxs + (t & 1) * 2048;
            float gate[4];
#pragma unroll
            for (int g = 0; g < 4; ++g)
                gate[g] = Ds0[cb * 36 + g * 8 + cjj] + Ds1[cb * 36 + g * 8 + cjj]
                        + gxb[cb * 32 + g * 8 + cjj];
            float cc = cs[tid];
            float cn = sigmoidf_(gate[1]) * cc + sigmoidf_(gate[0]) * tanhf(gate[2]);
            float hn = sigmoidf_(gate[3]) * tanhf(cn);
            cs[tid] = cn;
            g_hs[p ^ 1][(size_t)cb * HID + j0 + cjj] = __float2half(hn);
            if (t >= SRC) {
                size_t dr = (size_t)((t - SRC) * BATCH + cb) * HID + j0 + cjj;
                g_hall_b[dr] = __float2bfloat16(hn);
            }
        }

        // ---- distributed grid barrier (slot array, no atomics) ----
        __syncthreads();
        if (tid == 0) { __threadfence(); g_arrivev[bid] = t + 1; }
        if (tid < PCTAS) { while (g_arrivev[tid] < t + 1) {} }
        if (bid == 0 && tid == 0) { __threadfence(); g_genv = t + 1; }
        __syncthreads();

        if (t + 1 < NSTEP) {
            cp16(smb + PS_GX + (uint32_t)(((t + 1) & 1) * 8192 + gx_b * 128 + gx_g * 32 + gx_h * 16),
                 &g_gx[(size_t)((t + 1) * BATCH + gx_b) * G4 + gx_g * 512 + j0 + gx_h * 4]);
            CP_COMMIT();
        }
    }
}

// ---- one logits tile: 128m x 256n GEMM + fused LSE partials ----
__device__ void logits_tile(char* sm2, int m0, int ntile, const float* __restrict__ bout) {
    const uint32_t sbase = smem_u32(sm2);
    const int tid = threadIdx.x;
    const int l = tid & 31;
    const int w = tid >> 5;
    const int wr = w & 3;
    const int wc = w >> 2;
    const int n0 = ntile * 256;

    float* bias_s = (float*)(sm2 + LGB_BIAS);
    float* pm = (float*)(sm2 + LGB_PM);
    float* ps = (float*)(sm2 + LGB_PSUM);
    if (tid < 256) bias_s[tid] = bout[n0 + tid];

    float acc[2][8][4];
#pragma unroll
    for (int i = 0; i < 2; ++i)
#pragma unroll
        for (int j = 0; j < 8; ++j)
#pragma unroll
            for (int q = 0; q < 4; ++q) acc[i][j][q] = 0.0f;

    const int a_row = wr * 32 + (l & 7) + ((l & 8) ? 8 : 0);
    const int a_k8  = (l & 16) ? 8 : 0;
    const int b4_n  = (l & 7) + ((l & 16) ? 8 : 0);
    const int b4_k8 = (l & 8) ? 8 : 0;

#define LGB_STAGE_LD(kb, s) do {                                                      \
        uint32_t base = sbase + (s) * LGB_STG;                                        \
        _Pragma("unroll")                                                             \
        for (int i_ = 0; i_ < 2; ++i_) {                                              \
            int c_ = tid + i_ * 512;                                                  \
            int row_ = c_ >> 3;                                                       \
            int k8_ = (c_ & 7) * 8;                                                   \
            uint32_t so_ = (uint32_t)(row_ * 128 + ((k8_ * 2) ^ ((row_ & 7) << 4)));  \
            cp16(base + so_, &g_hall_b[(size_t)(m0 + row_) * HID + (kb) + k8_]);      \
        }                                                                             \
        _Pragma("unroll")                                                             \
        for (int i_ = 0; i_ < 4; ++i_) {                                              \
            int c_ = tid + i_ * 512;                                                  \
            int row_ = c_ >> 3;                                                       \
            int k8_ = (c_ & 7) * 8;                                                   \
            uint32_t so_ = (uint32_t)(row_ * 128 + ((k8_ * 2) ^ ((row_ & 7) << 4)));  \
            cp16(base + 16384 + so_, &g_wout_b[(size_t)(n0 + row_) * HID + (kb) + k8_]); \
        }                                                                             \
        CP_COMMIT();                                                                  \
    } while (0)

    LGB_STAGE_LD(0, 0);
    LGB_STAGE_LD(64, 1);
    for (int c = 0; c < 8; ++c) {
        if (c < 7) { CP_WAIT1(); } else { CP_WAIT0(); }
        __syncthreads();
        if (c < 6) LGB_STAGE_LD((c + 2) * 64, (c + 2) % 3);
        const uint32_t aB = sbase + (c % 3) * LGB_STG;
        const uint32_t bB = aB + 16384;
#pragma unroll
        for (int ks = 0; ks < 4; ++ks) {
            uint32_t a[2][4];
#pragma unroll
            for (int i = 0; i < 2; ++i) {
                int ar = a_row + i * 16;
                int ak = ks * 16 + a_k8;
                ldsm_x4(a[i], aB + ar * 128 + ((ak * 2) ^ ((ar & 7) << 4)));
            }
#pragma unroll
            for (int j16 = 0; j16 < 4; ++j16) {
                int bn = wc * 64 + j16 * 16 + b4_n;
                int bk = ks * 16 + b4_k8;
                uint32_t b[4];
                ldsm_x4_trans(b, bB + bn * 128 + ((bk * 2) ^ ((bn & 7) << 4)));
                mma_bf16(acc[0][j16 * 2],     a[0], b);
                mma_bf16(acc[1][j16 * 2],     a[1], b);
                mma_bf16(acc[0][j16 * 2 + 1], a[0], b + 2);
                mma_bf16(acc[1][j16 * 2 + 1], a[1], b + 2);
            }
        }
    }

#pragma unroll
    for (int i = 0; i < 2; ++i) {
#pragma unroll
        for (int half = 0; half < 2; ++half) {
            int row = wr * 32 + i * 16 + (l >> 2) + half * 8;
            float m = -INFINITY;
#pragma unroll
            for (int j = 0; j < 8; ++j) {
                int colL = wc * 64 + j * 8 + (l & 3) * 2;
                float v0 = acc[i][j][half * 2]     + bias_s[colL];
                float v1 = acc[i][j][half * 2 + 1] + bias_s[colL + 1];
                m = fmaxf(m, fmaxf(v0, v1));
            }
            float sx = 0.0f;
#pragma unroll
            for (int j = 0; j < 8; ++j) {
                int colL = wc * 64 + j * 8 + (l & 3) * 2;
                sx += fexp(acc[i][j][half * 2]     + bias_s[colL]     - m);
                sx += fexp(acc[i][j][half * 2 + 1] + bias_s[colL + 1] - m);
            }
#pragma unroll
            for (int d = 1; d < 4; d <<= 1) {
                float mo = __shfl_xor_sync(0xffffffffu, m, d);
                float so = __shfl_xor_sync(0xffffffffu, sx, d);
                float mm = fmaxf(m, mo);
                sx = sx * fexp(m - mm) + so * fexp(mo - mm);
                m = mm;
            }
            if ((l & 3) == 0) {
                pm[row * 4 + wc] = m;
                ps[row * 4 + wc] = sx;
            }
        }
    }
    __syncthreads();

    if (tid < 128) {
        float m = pm[tid * 4];
#pragma unroll
        for (int q = 1; q < 4; ++q) m = fmaxf(m, pm[tid * 4 + q]);
        float sx = 0.0f;
#pragma unroll
        for (int q = 0; q < 4; ++q) sx += ps[tid * 4 + q] * fexp(pm[tid * 4 + q] - m);
        int gr = m0 + tid;
        if (gr < DROWS) {
            g_pmax[(size_t)gr * VT2 + ntile] = m;
            g_psum[(size_t)gr * VT2 + ntile] = sx;
        }
    }
}

// ---- fused kernel ----
__global__ __launch_bounds__(512, 1) void fused_kernel(const float* __restrict__ bout) {
    extern __shared__ __align__(16) char sm[];
    const int tid = threadIdx.x;

    if (blockIdx.x < PCTAS) {
        lstm_recur(sm);
        __syncthreads();
    }

    // logits work loop (all CTAs; recurrence CTAs join after finishing)
    int* slot = (int*)(sm + FS_SLOT);
    for (;;) {
        if (tid == 0) {
            int tile = (int)atomicAdd(&g_tile, 1u);
            *slot = tile;
            if (tile < NTILES) {
                int m = tile / VT2;
                int ready = SRC + 2 * m + 2;
                if (ready > NSTEP) ready = NSTEP;
                while (g_genv < ready) __nanosleep(64);
            }
        }
        __syncthreads();
        int tile = *slot;
        if (tile >= NTILES) break;
        logits_tile(sm, (tile / VT2) * 128, tile % VT2, bout);
        __syncthreads();
    }
}

// ================= combine partials -> per-(d,b) loss =================
__global__ void combine_loss(const int* __restrict__ target_lines,
                             const float* __restrict__ bout) {
    __shared__ float sred[128];
    const int b = blockIdx.x;
    const int d = blockIdx.y;
    const int bs = d * BATCH + b;
    const int tid = threadIdx.x;

    float m = -INFINITY;
    for (int p = tid; p < VT2; p += 128) m = fmaxf(m, g_pmax[(size_t)bs * VT2 + p]);
    sred[tid] = m;
    __syncthreads();
    for (int s = 64; s > 0; s >>= 1) {
        if (tid < s) sred[tid] = fmaxf(sred[tid], sred[tid + s]);
        __syncthreads();
    }
    const float gmax = sred[0];
    __syncthreads();

    float sum = 0.0f;
    for (int p = tid; p < VT2; p += 128)
        sum += g_psum[(size_t)bs * VT2 + p] * __expf(g_pmax[(size_t)bs * VT2 + p] - gmax);
    sred[tid] = sum;
    __syncthreads();
    for (int s = 64; s > 0; s >>= 1) {
        if (tid < s) sred[tid] += sred[tid + s];
        __syncthreads();
    }
    const float gsum = sred[0];
    __syncthreads();

    const int nxt = target_lines[(d + 1) * BATCH + b];
    const __nv_bfloat16* hrow = &g_hall_b[(size_t)bs * HID];
    const __nv_bfloat16* wrow = &g_wout_b[(size_t)nxt * HID];
    float ds = 0.0f;
#pragma unroll
    for (int q = 0; q < 4; ++q)
        ds += __bfloat162float(hrow[tid * 4 + q]) * __bfloat162float(wrow[tid * 4 + q]);
    sred[tid] = ds;
    __syncthreads();
    for (int s = 64; s > 0; s >>= 1) {
        if (tid < s) sred[tid] += sred[tid + s];
        __syncthreads();
    }
    if (tid == 0)
        g_losses[bs] = -(sred[0] + bout[nxt] - gmax - logf(gsum));
}

// ---------------- final deterministic sum ----------------
__global__ void final_kernel(float* __restrict__ out) {
    __shared__ float sred[256];
    const int tid = threadIdx.x;
    float s = 0.0f;
    for (int i = tid; i < DROWS; i += 256) s += g_losses[i];
    sred[tid] = s;
    __syncthreads();
    for (int st = 128; st > 0; st >>= 1) {
        if (tid < st) sred[tid] += sred[tid + st];
        __syncthreads();
    }
    if (tid == 0) out[0] = sred[0] * (1.0f / (float)BATCH);
}

// ---------------- host ----------------
extern "C" void kernel_launch(void* const* d_in, const int* in_sizes, int n_in,
                              void* d_out, int out_size) {
    (void)in_sizes; (void)n_in; (void)out_size;
    const int*   input_lines  = (const int*)  d_in[0];
    const int*   target_lines = (const int*)  d_in[1];
    const float* emb_in       = (const float*)d_in[2];
    const float* emb_tgt      = (const float*)d_in[3];
    const float* W_ih_enc     = (const float*)d_in[4];
    const float* W_hh_enc     = (const float*)d_in[5];
    const float* b_ih_enc     = (const float*)d_in[6];
    const float* b_hh_enc     = (const float*)d_in[7];
    const float* W_ih_dec     = (const float*)d_in[8];
    const float* W_hh_dec     = (const float*)d_in[9];
    const float* b_ih_dec     = (const float*)d_in[10];
    const float* b_hh_dec     = (const float*)d_in[11];
    const float* W_out        = (const float*)d_in[12];
    const float* b_out        = (const float*)d_in[13];
    float* out = (float*)d_out;

    cudaFuncSetAttribute(gx_mma,       cudaFuncAttributeMaxDynamicSharedMemorySize, GX_SMEM);
    cudaFuncSetAttribute(fused_kernel, cudaFuncAttributeMaxDynamicSharedMemorySize, FS_SMEM);

    init_kernel<<<256, 256>>>();

    conv_weights<<<4096, 256>>>(W_ih_enc, W_ih_dec, W_hh_enc, W_hh_dec);
    conv_wout<<<VOCAB * HID / 4 / 256, 256>>>(W_out);
    prep_x<<<XROWS_PAD, 64>>>(input_lines, target_lines, emb_in, emb_tgt);

    gx_mma<<<dim3(16, XROWS_PAD / 128), 256, GX_SMEM>>>(b_ih_enc, b_hh_enc, b_ih_dec, b_hh_dec);

    fused_kernel<<<FCTAS, 512, FS_SMEM>>>(b_out);

    combine_loss<<<dim3(BATCH, TGT), 128>>>(target_lines, b_out);
    final_kernel<<<1, 256>>>(out);
}